// round 1
// baseline (speedup 1.0000x reference)
#include <cuda_runtime.h>
#include <math.h>

#define NOISE_SCALE 0.1f
#define NOISE_RATIO 0.3f
#define ADAPTIVE_FACTOR 1.0f
#define MAX_NOISE 1.0f

#define B_ROWS 4096
#define D_COLS 4096
#define C_CLASSES 1000

// Per-row noise scale scratch (no device allocations allowed).
__device__ float g_scales[B_ROWS];

// ---------------------------------------------------------------------------
// Kernel 1: per-row confidence from model_output [B, C]
// confidence = max softmax prob = 1 / sum_i exp(l_i - max)
// scale = min(NOISE_SCALE * (1 + ADAPTIVE_FACTOR * confidence), MAX_NOISE)
// One 256-thread block per row.
// ---------------------------------------------------------------------------
__global__ __launch_bounds__(256) void conf_kernel(const float* __restrict__ mo) {
    const int row = blockIdx.x;
    const float* p = mo + (long long)row * C_CLASSES;
    const int tid = threadIdx.x;

    __shared__ float sred[256];

    // 1) row max
    float m = -INFINITY;
    for (int i = tid; i < C_CLASSES; i += 256) m = fmaxf(m, p[i]);
    sred[tid] = m;
    __syncthreads();
    #pragma unroll
    for (int off = 128; off >= 1; off >>= 1) {
        if (tid < off) sred[tid] = fmaxf(sred[tid], sred[tid + off]);
        __syncthreads();
    }
    m = sred[0];
    __syncthreads();

    // 2) sum exp(l - m)
    float s = 0.0f;
    for (int i = tid; i < C_CLASSES; i += 256) s += expf(p[i] - m);
    sred[tid] = s;
    __syncthreads();
    #pragma unroll
    for (int off = 128; off >= 1; off >>= 1) {
        if (tid < off) sred[tid] += sred[tid + off];
        __syncthreads();
    }

    if (tid == 0) {
        float conf = 1.0f / sred[0];
        g_scales[row] = fminf(NOISE_SCALE * (1.0f + ADAPTIVE_FACTOR * conf), MAX_NOISE);
    }
}

// ---------------------------------------------------------------------------
// Kernel 2: elementwise noise add, float4 vectorized.
// out = x + (rand_u < NOISE_RATIO ? noise_std * scale[row] : 0)
// D_COLS/4 = 1024 float4 per row -> row = i >> 10
// ---------------------------------------------------------------------------
__global__ __launch_bounds__(256) void noise_kernel(const float4* __restrict__ x,
                                                    const float4* __restrict__ ru,
                                                    const float4* __restrict__ ns,
                                                    float4* __restrict__ out,
                                                    int n4) {
    int i = blockIdx.x * blockDim.x + threadIdx.x;
    if (i >= n4) return;
    const float s = g_scales[i >> 10];  // D_COLS/4 = 1024
    float4 xv = x[i];
    float4 rv = ru[i];
    float4 nv = ns[i];
    float4 o;
    o.x = xv.x + (rv.x < NOISE_RATIO ? nv.x * s : 0.0f);
    o.y = xv.y + (rv.y < NOISE_RATIO ? nv.y * s : 0.0f);
    o.z = xv.z + (rv.z < NOISE_RATIO ? nv.z * s : 0.0f);
    o.w = xv.w + (rv.w < NOISE_RATIO ? nv.w * s : 0.0f);
    out[i] = o;
}

extern "C" void kernel_launch(void* const* d_in, const int* in_sizes, int n_in,
                              void* d_out, int out_size) {
    // metadata order: x [B*D], model_output [B*C], rand_u [B*D], noise_std [B*D]
    const float* x  = (const float*)d_in[0];
    const float* mo = (const float*)d_in[1];
    const float* ru = (const float*)d_in[2];
    const float* ns = (const float*)d_in[3];
    float* out = (float*)d_out;

    // Stage 1: per-row scale
    conf_kernel<<<B_ROWS, 256>>>(mo);

    // Stage 2: elementwise
    const int n4 = (B_ROWS * D_COLS) / 4;  // 4,194,304
    noise_kernel<<<(n4 + 255) / 256, 256>>>((const float4*)x, (const float4*)ru,
                                            (const float4*)ns, (float4*)out, n4);
}

// round 2
// speedup vs baseline: 1.2423x; 1.2423x over previous
#include <cuda_runtime.h>
#include <math.h>

#define NOISE_SCALE 0.1f
#define NOISE_RATIO 0.3f
#define ADAPTIVE_FACTOR 1.0f
#define MAX_NOISE 1.0f

#define B_ROWS 4096
#define D_COLS 4096
#define C_CLASSES 1000
#define C4 (C_CLASSES / 4)   // 250 float4 per model_output row
#define D4 (D_COLS / 4)      // 1024 float4 per data row

// One block per row: compute softmax confidence for the row (single pass,
// data kept in registers), then stream the elementwise noise add for the row.
__global__ __launch_bounds__(256) void fused_kernel(const float4* __restrict__ x,
                                                    const float4* __restrict__ mo4,
                                                    const float4* __restrict__ ru,
                                                    const float4* __restrict__ ns,
                                                    float4* __restrict__ out) {
    const int row = blockIdx.x;
    const int tid = threadIdx.x;
    const int lane = tid & 31;
    const int warp = tid >> 5;

    __shared__ float sred[8];
    __shared__ float s_scale;

    // ---- load this thread's slice of the logits row (<=1 float4) ----
    float4 v;
    const bool have = (tid < C4);
    if (have) v = mo4[(long long)row * C4 + tid];
    else      v = make_float4(-INFINITY, -INFINITY, -INFINITY, -INFINITY);

    // ---- row max ----
    float m = fmaxf(fmaxf(v.x, v.y), fmaxf(v.z, v.w));
    #pragma unroll
    for (int off = 16; off >= 1; off >>= 1)
        m = fmaxf(m, __shfl_xor_sync(0xffffffffu, m, off));
    if (lane == 0) sred[warp] = m;
    __syncthreads();
    if (warp == 0) {
        float mm = sred[lane & 7];
        #pragma unroll
        for (int off = 4; off >= 1; off >>= 1)
            mm = fmaxf(mm, __shfl_xor_sync(0xffffffffu, mm, off));
        if (lane == 0) sred[0] = mm;
    }
    __syncthreads();
    m = sred[0];

    // ---- sum of exp(l - m), data already in registers ----
    float s = 0.0f;
    if (have)
        s = __expf(v.x - m) + __expf(v.y - m) + __expf(v.z - m) + __expf(v.w - m);
    #pragma unroll
    for (int off = 16; off >= 1; off >>= 1)
        s += __shfl_xor_sync(0xffffffffu, s, off);
    __syncthreads();   // reuse sred safely
    if (lane == 0) sred[warp] = s;
    __syncthreads();
    if (warp == 0) {
        float ss = sred[lane & 7];
        #pragma unroll
        for (int off = 4; off >= 1; off >>= 1)
            ss += __shfl_xor_sync(0xffffffffu, ss, off);
        if (lane == 0) {
            float conf = 1.0f / ss;
            s_scale = fminf(NOISE_SCALE * (1.0f + ADAPTIVE_FACTOR * conf), MAX_NOISE);
        }
    }
    __syncthreads();
    const float scale = s_scale;

    // ---- elementwise noise add for this row: 1024 float4, 4 per thread ----
    const long long base = (long long)row * D4;
    #pragma unroll
    for (int j = 0; j < D4 / 256; j++) {
        const long long i = base + tid + j * 256;
        float4 xv = __ldcs(&x[i]);
        float4 rv = __ldcs(&ru[i]);
        float4 nv = __ldcs(&ns[i]);
        float4 o;
        o.x = xv.x + (rv.x < NOISE_RATIO ? nv.x * scale : 0.0f);
        o.y = xv.y + (rv.y < NOISE_RATIO ? nv.y * scale : 0.0f);
        o.z = xv.z + (rv.z < NOISE_RATIO ? nv.z * scale : 0.0f);
        o.w = xv.w + (rv.w < NOISE_RATIO ? nv.w * scale : 0.0f);
        out[i] = o;
    }
}

extern "C" void kernel_launch(void* const* d_in, const int* in_sizes, int n_in,
                              void* d_out, int out_size) {
    const float* x  = (const float*)d_in[0];
    const float* mo = (const float*)d_in[1];
    const float* ru = (const float*)d_in[2];
    const float* ns = (const float*)d_in[3];
    float* out = (float*)d_out;

    fused_kernel<<<B_ROWS, 256>>>((const float4*)x, (const float4*)mo,
                                  (const float4*)ru, (const float4*)ns,
                                  (float4*)out);
}